// round 2
// baseline (speedup 1.0000x reference)
#include <cuda_runtime.h>
#include <math.h>
#include <stdint.h>

typedef unsigned long long ull;

constexpr int Bn=2, Vn=8, Cn=64, Hn=128, Wn=128, An=256;
constexpr int HWn=Hn*Wn, Pn=An*An;
constexpr int C3n=194, COn=192, HIDn=48;
constexpr int CIN1P=200;

constexpr size_t CTXN=(size_t)Bn*C3n*Pn;
constexpr size_t CNTN=(size_t)Bn*3*Pn;
constexpr size_t OFF_COV =(size_t)3*Bn*Cn*Pn;
constexpr size_t OFF_UNC =OFF_COV+(size_t)Bn*Pn;
constexpr size_t OFF_CONF=OFF_UNC+(size_t)Bn*Pn;

__device__ float  g_ctx[CTXN];
__device__ float  g_cnt[CNTN];
__device__ float  g_uraw[(size_t)Bn*Pn];
__device__ int    g_umax[Bn];
__device__ int    g_idx[Bn*Vn*HWn];
__device__ float  g_wts[3][Bn*Vn*HWn];
__device__ float  g_h1[(size_t)Bn*COn*Pn];
__device__ float  g_h2[(size_t)Bn*COn*Pn];
__device__ float  g_wT1[(size_t)CIN1P*9*COn];
__device__ float  g_wT2[(size_t)COn*9*COn];
__device__ double g_csum[Bn*COn*2];
__device__ float  g_sA[Bn*COn], g_sB[Bn*COn];
__device__ float  g_gate[Bn*COn];

__device__ __forceinline__ float siluf(float x){ return x/(1.f+__expf(-x)); }
__device__ __forceinline__ float sigf(float x){ return 1.f/(1.f+__expf(-x)); }
__device__ __forceinline__ ull pack2(float v){ ull r; asm("mov.b64 %0,{%1,%1};":"=l"(r):"f"(v)); return r; }
__device__ __forceinline__ void fma2(ull&a, ull x, ull w){ asm("fma.rn.f32x2 %0,%1,%2,%0;":"+l"(a):"l"(x),"l"(w)); }
__device__ __forceinline__ void unpack2(ull v, float&lo, float&hi){ asm("mov.b64 {%0,%1},%2;":"=f"(lo),"=f"(hi):"l"(v)); }

__global__ void k_zero(){
    size_t st=(size_t)gridDim.x*blockDim.x;
    for(size_t i=(size_t)blockIdx.x*blockDim.x+threadIdx.x; i<CTXN+CNTN; i+=st){
        if(i<CTXN) g_ctx[i]=0.f; else g_cnt[i-CTXN]=0.f;
    }
    if(blockIdx.x==0 && threadIdx.x<Bn) g_umax[threadIdx.x]=0;
}

__global__ void k_prep(const float* __restrict__ uvs, const float* __restrict__ msk,
                       const float* __restrict__ wg, const float* __restrict__ wb,
                       const float* __restrict__ wh){
    int i=blockIdx.x*blockDim.x+threadIdx.x;
    if(i>=Bn*Vn*HWn) return;
    float u=uvs[2*i], v=uvs[2*i+1];
    bool fin=isfinite(u)&&isfinite(v);
    float su=fin?u:0.f, sv=fin?v:0.f;
    int xi=(int)rintf(fminf(fmaxf(su,0.f),1.f)*(float)(An-1));
    int yi=(int)rintf((1.f-fminf(fmaxf(sv,0.f),1.f))*(float)(An-1));
    g_idx[i]=yi*An+xi;
    bool mv=(msk[i]>0.5f)&&fin;
    int bv=i/HWn;
    float w0=fmaxf(wg[bv],0.f), w1=fmaxf(wb[bv],0.f), w2=fmaxf(wh[bv],0.f);
    g_wts[0][i]=(mv&&w0>0.f)?w0:0.f;
    g_wts[1][i]=(mv&&w1>0.f)?w1:0.f;
    g_wts[2][i]=(mv&&w2>0.f)?w2:0.f;
}

__global__ void k_scatter(const float* __restrict__ vf){
    int bv=blockIdx.y;
    int px=blockIdx.x*blockDim.x+threadIdx.x;
    int i=bv*HWn+px;
    int b=bv>>3;
    int idx=g_idx[i];
    float w0=g_wts[0][i], w1=g_wts[1][i], w2=g_wts[2][i];
    if(w0<=0.f && w1<=0.f && w2<=0.f) return;
    float* base=g_ctx+(size_t)b*C3n*Pn+idx;
    const float* vp=vf+(size_t)bv*Cn*HWn+px;
    #pragma unroll 4
    for(int c=0;c<Cn;c++){
        float v=vp[(size_t)c*HWn];
        if(w0>0.f) atomicAdd(base+(size_t)c*Pn, w0*v);
        if(w1>0.f) atomicAdd(base+(size_t)(Cn+c)*Pn, w1*v);
        if(w2>0.f) atomicAdd(base+(size_t)(2*Cn+c)*Pn, w2*v);
    }
    if(w0>0.f) atomicAdd(&g_cnt[((size_t)b*3+0)*Pn+idx], w0);
    if(w1>0.f) atomicAdd(&g_cnt[((size_t)b*3+1)*Pn+idx], w1);
    if(w2>0.f) atomicAdd(&g_cnt[((size_t)b*3+2)*Pn+idx], w2);
}

__global__ void k_finalize(){
    int i=blockIdx.x*blockDim.x+threadIdx.x;
    int b=i>>16, px=i&(Pn-1);
    size_t base=(size_t)b*C3n*Pn+px;
    float c0=g_cnt[((size_t)b*3+0)*Pn+px];
    float c1=g_cnt[((size_t)b*3+1)*Pn+px];
    float c2=g_cnt[((size_t)b*3+2)*Pn+px];
    float i0=1.f/fmaxf(c0,1.f), i1=1.f/fmaxf(c1,1.f), i2=1.f/fmaxf(c2,1.f);
    float ss=0.f;
    #pragma unroll 4
    for(int c=0;c<Cn;c++){
        float g=g_ctx[base+(size_t)c*Pn]*i0;
        float h=g_ctx[base+(size_t)(Cn+c)*Pn]*i1;
        float t=g_ctx[base+(size_t)(2*Cn+c)*Pn]*i2;
        g_ctx[base+(size_t)c*Pn]=g;
        g_ctx[base+(size_t)(Cn+c)*Pn]=h;
        g_ctx[base+(size_t)(2*Cn+c)*Pn]=t;
        float m=(g+h+t)*(1.f/3.f);
        float dg=g-m, dh=h-m, dt=t-m;
        ss+=dg*dg+dh*dh+dt*dt;
    }
    float cov=((c0>0.f?1.f:0.f)+(c1>0.f?1.f:0.f)+(c2>0.f?1.f:0.f))*(1.f/3.f);
    cov=fminf(cov,1.f);
    float uraw=sqrtf(ss*(1.f/(3.f*Cn)));
    g_ctx[base+(size_t)192*Pn]=cov;
    g_uraw[i]=uraw;
    float m=uraw;
    #pragma unroll
    for(int o=16;o>0;o>>=1) m=fmaxf(m,__shfl_xor_sync(0xffffffffu,m,o));
    if((threadIdx.x&31)==0) atomicMax(&g_umax[b], __float_as_int(m));
}

__global__ void k_uncert(float* __restrict__ dout){
    int i=blockIdx.x*blockDim.x+threadIdx.x;
    int b=i>>16, px=i&(Pn-1);
    size_t base=(size_t)b*C3n*Pn+px;
    float cov=g_ctx[base+(size_t)192*Pn];
    float sc=fmaxf(__int_as_float(g_umax[b]),1e-6f);
    float un=fminf(fmaxf(g_uraw[i]/sc,0.f),1.f)*cov;
    g_ctx[base+(size_t)193*Pn]=un;
    dout[OFF_COV+i]=cov;
    dout[OFF_UNC+i]=un;
}

__global__ void k_conf(const float* __restrict__ cw, const float* __restrict__ cb,
                       float* __restrict__ dout){
    __shared__ float s_cw[3*C3n];
    for(int l=threadIdx.x;l<3*C3n;l+=blockDim.x) s_cw[l]=cw[l];
    __syncthreads();
    int i=blockIdx.x*blockDim.x+threadIdx.x;
    int b=i>>16, px=i&(Pn-1);
    const float* xp=g_ctx+(size_t)b*C3n*Pn+px;
    float a0=cb[0], a1=cb[1], a2=cb[2];
    #pragma unroll 2
    for(int ci=0;ci<C3n;ci++){
        float x=xp[(size_t)ci*Pn];
        a0+=x*s_cw[ci]; a1+=x*s_cw[C3n+ci]; a2+=x*s_cw[2*C3n+ci];
    }
    dout[OFF_CONF+((size_t)(b*3+0))*Pn+px]=sigf(a0);
    dout[OFF_CONF+((size_t)(b*3+1))*Pn+px]=sigf(a1);
    dout[OFF_CONF+((size_t)(b*3+2))*Pn+px]=sigf(a2);
}

template<int MODE>
__global__ void k_wtrans(const float* __restrict__ w){
    constexpr int CIN =(MODE==0)?C3n:COn;
    constexpr int CINP=(MODE==0)?CIN1P:COn;
    int n=CINP*9*COn;
    int i=blockIdx.x*blockDim.x+threadIdx.x;
    if(i>=n) return;
    int ci=i/(9*COn);
    int r=i-ci*(9*COn);
    int tap=r/COn, co=r-tap*COn;
    float v=(ci<CIN)?w[((size_t)co*CIN+ci)*9+tap]:0.f;
    if(MODE==0) g_wT1[i]=v; else g_wT2[i]=v;
}

template<int CIN, int NCH, int MODE>
__global__ void __launch_bounds__(256,1) k_conv(const float* __restrict__ bias){
    __shared__ __align__(16) float s_in[8][18*19];
    __shared__ __align__(16) float s_w[8][9][64];
    const float* in=(MODE==0)?g_ctx:g_h1;
    const float* wT=(MODE==0)?g_wT1:g_wT2;
    float* out     =(MODE==0)?g_h1 :g_h2;

    const int tid=threadIdx.x;
    const int cg=tid>>5, pg=tid&31;
    const int prow=pg>>1, pxo=(pg&1)*8;
    const int tile=blockIdx.x;
    const int tx=(tile&15)*16, ty=(tile>>4)*16;
    const int coT=blockIdx.y;
    const int b=blockIdx.z;
    const float* inB=in+(size_t)b*CIN*Pn;

    ull acc[8][4];
    #pragma unroll
    for(int p=0;p<8;p++){ acc[p][0]=0; acc[p][1]=0; acc[p][2]=0; acc[p][3]=0; }

    #pragma unroll 1
    for(int ch=0;ch<NCH;ch++){
        int ci0=ch*8;
        for(int l=tid;l<8*18*18;l+=256){
            int cil=l/324;
            int r=l-cil*324;
            int y=r/18, x=r-y*18;
            int ci=ci0+cil;
            int gy=ty-1+y, gx=tx-1+x;
            float v=0.f;
            if(ci<CIN && gy>=0 && gy<An && gx>=0 && gx<An)
                v=inB[(size_t)ci*Pn+gy*An+gx];
            s_in[cil][y*19+x]=v;
        }
        float* swf=&s_w[0][0][0];
        for(int l=tid;l<8*9*64;l+=256){
            int cil=l/576;
            int r=l-cil*576;
            int tap=r/64, co=r-tap*64;
            swf[l]=wT[((size_t)(ci0+cil)*9+tap)*COn+coT*64+co];
        }
        __syncthreads();

        #pragma unroll 2
        for(int ci=0;ci<8;ci++){
            #pragma unroll
            for(int kh=0;kh<3;kh++){
                const float* row=&s_in[ci][(prow+kh)*19+pxo];
                ull rd[10];
                #pragma unroll
                for(int k=0;k<10;k++) rd[k]=pack2(row[k]);
                #pragma unroll
                for(int kw=0;kw<3;kw++){
                    const ull* wp=reinterpret_cast<const ull*>(&s_w[ci][kh*3+kw][cg*8]);
                    ull w0=wp[0], w1=wp[1], w2=wp[2], w3=wp[3];
                    #pragma unroll
                    for(int p=0;p<8;p++){
                        fma2(acc[p][0], rd[p+kw], w0);
                        fma2(acc[p][1], rd[p+kw], w1);
                        fma2(acc[p][2], rd[p+kw], w2);
                        fma2(acc[p][3], rd[p+kw], w3);
                    }
                }
            }
        }
        __syncthreads();
    }

    const int ybase=ty+prow, xbase=tx+pxo;
    #pragma unroll
    for(int oc=0;oc<8;oc++){
        int co=coT*64+cg*8+oc;
        float bv=bias[co];
        float vals[8];
        #pragma unroll
        for(int p=0;p<8;p++){
            float lo,hi; unpack2(acc[p][oc>>1],lo,hi);
            vals[p]=((oc&1)?hi:lo)+bv;
        }
        float* op=out+((size_t)(b*COn+co)*An+ybase)*An+xbase;
        reinterpret_cast<float4*>(op)[0]=make_float4(vals[0],vals[1],vals[2],vals[3]);
        reinterpret_cast<float4*>(op)[1]=make_float4(vals[4],vals[5],vals[6],vals[7]);
    }
}

template<int MODE>
__global__ void k_chansum(){
    __shared__ double ss[256], sq[256];
    const float* x=(MODE==0)?g_h1:g_h2;
    int bc=blockIdx.x;
    const float* p=x+(size_t)bc*Pn;
    double s=0.0, q=0.0;
    for(int i=threadIdx.x;i<Pn;i+=256){
        double v=(double)p[i];
        s+=v; q+=v*v;
    }
    ss[threadIdx.x]=s; sq[threadIdx.x]=q;
    __syncthreads();
    for(int st=128;st>0;st>>=1){
        if(threadIdx.x<st){ ss[threadIdx.x]+=ss[threadIdx.x+st]; sq[threadIdx.x]+=sq[threadIdx.x+st]; }
        __syncthreads();
    }
    if(threadIdx.x==0){ g_csum[bc*2]=ss[0]; g_csum[bc*2+1]=sq[0]; }
}

__global__ void k_stats(const float* __restrict__ scale, const float* __restrict__ shift){
    __shared__ float gm[16], gr[16];
    int t=threadIdx.x;
    if(t<Bn*8){
        int b=t/8, g=t%8;
        double s=0.0, q=0.0;
        for(int c=0;c<24;c++){
            s+=g_csum[((size_t)b*COn+g*24+c)*2];
            q+=g_csum[((size_t)b*COn+g*24+c)*2+1];
        }
        double N=24.0*(double)Pn;
        double mean=s/N;
        double var=q/N-mean*mean;
        gm[t]=(float)mean;
        gr[t]=(float)(1.0/sqrt(var+1e-5));
    }
    __syncthreads();
    if(t<Bn*COn){
        int b=t/COn, c=t%COn, g=c/24;
        float a=gr[b*8+g]*scale[c];
        g_sA[t]=a;
        g_sB[t]=shift[c]-gm[b*8+g]*a;
    }
}

template<int MODE>
__global__ void k_apply(){
    float* x=(MODE==0)?g_h1:g_h2;
    size_t i=(size_t)blockIdx.x*blockDim.x+threadIdx.x;
    int bc=(int)(i>>16);
    float v=x[i]*g_sA[bc]+g_sB[bc];
    x[i]=siluf(v);
}

__global__ void k_gate(const float* __restrict__ gw1, const float* __restrict__ gb1,
                       const float* __restrict__ gw2, const float* __restrict__ gb2){
    __shared__ float pooled[COn];
    __shared__ float hbuf[HIDn];
    for(int b=0;b<Bn;b++){
        for(int c=threadIdx.x;c<COn;c+=blockDim.x)
            pooled[c]=(float)(g_csum[((size_t)b*COn+c)*2]/(double)Pn);
        __syncthreads();
        if(threadIdx.x<HIDn){
            float s=gb1[threadIdx.x];
            for(int c=0;c<COn;c++) s+=gw1[threadIdx.x*COn+c]*pooled[c];
            hbuf[threadIdx.x]=siluf(s);
        }
        __syncthreads();
        if(threadIdx.x<COn){
            float s=gb2[threadIdx.x];
            for(int j=0;j<HIDn;j++) s+=gw2[threadIdx.x*HIDn+j]*hbuf[j];
            g_gate[b*COn+threadIdx.x]=0.5f+sigf(s);
        }
        __syncthreads();
    }
}

__global__ void __launch_bounds__(256) k_res_combine(
    const float* __restrict__ rpw, const float* __restrict__ rpb,
    const float* __restrict__ prs, const float* __restrict__ pmix,
    float* __restrict__ dout){
    __shared__ float s_w[97*64];
    const int br=blockIdx.y, b=blockIdx.z;
    const int og=threadIdx.x>>6, pl=threadIdx.x&63;
    const int pxb=blockIdx.x*256;
    const float* ctxb=g_ctx+(size_t)b*C3n*Pn;

    float acc[4][16];
    #pragma unroll
    for(int k=0;k<4;k++)
        #pragma unroll
        for(int o=0;o<16;o++) acc[k][o]=0.f;

    #pragma unroll 1
    for(int half=0;half<2;half++){
        int ci0=half*97;
        for(int l=threadIdx.x;l<97*64;l+=256){
            int ci=l>>6, o=l&63;
            s_w[l]=rpw[(size_t)(br*64+o)*C3n+ci0+ci];
        }
        __syncthreads();
        #pragma unroll 1
        for(int ci=0;ci<97;ci++){
            const float* xp=ctxb+(size_t)(ci0+ci)*Pn+pxb+pl;
            float x0=xp[0], x1=xp[64], x2=xp[128], x3=xp[192];
            const float* wrow=&s_w[ci*64+og*16];
            #pragma unroll
            for(int oc=0;oc<16;oc++){
                float w=wrow[oc];
                acc[0][oc]+=x0*w; acc[1][oc]+=x1*w;
                acc[2][oc]+=x2*w; acc[3][oc]+=x3*w;
            }
        }
        __syncthreads();
    }

    const float trs=tanhf(prs[0]);
    const float ms=tanhf(pmix[0]);
    #pragma unroll
    for(int k=0;k<4;k++){
        int px=pxb+pl+k*64;
        float confv=dout[OFF_CONF+((size_t)(b*3+br))*Pn+px];
        #pragma unroll
        for(int oc=0;oc<16;oc++){
            int c=og*16+oc;
            int co=br*64+c;
            float res=acc[k][oc]+rpb[co];
            float h=g_h2[((size_t)(b*COn)+co)*Pn+px];
            float refine=h*g_gate[b*COn+co]+trs*res;
            float feat=ctxb[(size_t)co*Pn+px];
            dout[(size_t)br*((size_t)Bn*Cn*Pn)+((size_t)(b*Cn+c))*Pn+px]
                =feat+ms*refine*confv;
        }
    }
}

extern "C" void kernel_launch(void* const* d_in, const int* in_sizes, int n_in,
                              void* d_out, int out_size){
    const float* vf   =(const float*)d_in[0];
    const float* uvs  =(const float*)d_in[1];
    const float* msk  =(const float*)d_in[2];
    const float* wg   =(const float*)d_in[3];
    const float* wb   =(const float*)d_in[4];
    const float* wh   =(const float*)d_in[5];
    // d_in[6] = atlas_size (256, hardcoded)
    const float* c1w  =(const float*)d_in[7];
    const float* c1b  =(const float*)d_in[8];
    const float* g1s  =(const float*)d_in[9];
    const float* g1b  =(const float*)d_in[10];
    const float* c2w  =(const float*)d_in[11];
    const float* c2b  =(const float*)d_in[12];
    const float* g2s  =(const float*)d_in[13];
    const float* g2b  =(const float*)d_in[14];
    const float* gw1  =(const float*)d_in[15];
    const float* gb1  =(const float*)d_in[16];
    const float* gw2  =(const float*)d_in[17];
    const float* gb2  =(const float*)d_in[18];
    const float* rpw  =(const float*)d_in[19];
    const float* rpb  =(const float*)d_in[20];
    const float* rs   =(const float*)d_in[21];
    const float* cfw  =(const float*)d_in[22];
    const float* cfb  =(const float*)d_in[23];
    const float* mixs =(const float*)d_in[24];
    float* dout=(float*)d_out;

    k_zero<<<512,256>>>();
    k_prep<<<1024,256>>>(uvs,msk,wg,wb,wh);
    k_wtrans<0><<<(CIN1P*9*COn+255)/256,256>>>(c1w);
    k_wtrans<1><<<(COn*9*COn+255)/256,256>>>(c2w);
    k_scatter<<<dim3(64,16),256>>>(vf);
    k_finalize<<<512,256>>>();
    k_uncert<<<512,256>>>(dout);
    k_conf<<<512,256>>>(cfw,cfb,dout);
    k_conv<C3n,25,0><<<dim3(256,3,2),256>>>(c1b);
    k_chansum<0><<<Bn*COn,256>>>();
    k_stats<<<1,384>>>(g1s,g1b);
    k_apply<0><<<98304,256>>>();
    k_conv<COn,24,1><<<dim3(256,3,2),256>>>(c2b);
    k_chansum<1><<<Bn*COn,256>>>();
    k_stats<<<1,384>>>(g2s,g2b);
    k_apply<1><<<98304,256>>>();
    k_chansum<1><<<Bn*COn,256>>>();   // post-silu sums for channel-gate pooling
    k_gate<<<1,192>>>(gw1,gb1,gw2,gb2);
    k_res_combine<<<dim3(256,3,2),256>>>(rpw,rpb,rs,mixs,dout);
}

// round 3
// speedup vs baseline: 1.3987x; 1.3987x over previous
#include <cuda_runtime.h>
#include <math.h>
#include <stdint.h>

typedef unsigned long long ull;

constexpr int Bn=2, Vn=8, Cn=64, An=256;
constexpr int HWn=128*128, Pn=An*An;
constexpr int C3n=194, COn=192, HIDn=48, CIN1P=200;

constexpr size_t CTXN=(size_t)Bn*C3n*Pn;
constexpr size_t CNTN=(size_t)Bn*3*Pn;
constexpr size_t OFF_COV =(size_t)3*Bn*Cn*Pn;
constexpr size_t OFF_UNC =OFF_COV+(size_t)Bn*Pn;
constexpr size_t OFF_CONF=OFF_UNC+(size_t)Bn*Pn;

__device__ float  g_ctx[CTXN];
__device__ float  g_cnt[CNTN];
__device__ float  g_uraw[(size_t)Bn*Pn];
__device__ int    g_umax[Bn];
__device__ int    g_idx[Bn*Vn*HWn];
__device__ float  g_wts[3][Bn*Vn*HWn];
__device__ float  g_h1[(size_t)Bn*COn*Pn];
__device__ float  g_h2[(size_t)Bn*COn*Pn];
__device__ float  g_wT1[3*CIN1P*9*64];
__device__ float  g_wT2[3*COn*9*64];
__device__ float  g_csum[Bn*COn*2];
__device__ float  g_sA[Bn*COn], g_sB[Bn*COn];
__device__ float  g_gate[Bn*COn];

__device__ __forceinline__ float siluf(float x){ return x/(1.f+__expf(-x)); }
__device__ __forceinline__ float sigf(float x){ return 1.f/(1.f+__expf(-x)); }
__device__ __forceinline__ ull pack2(float v){ ull r; asm("mov.b64 %0,{%1,%1};":"=l"(r):"f"(v)); return r; }
__device__ __forceinline__ void fma2(ull&a, ull x, ull w){ asm("fma.rn.f32x2 %0,%1,%2,%0;":"+l"(a):"l"(x),"l"(w)); }
__device__ __forceinline__ void unpack2(ull v, float&lo, float&hi){ asm("mov.b64 {%0,%1},%2;":"=f"(lo),"=f"(hi):"l"(v)); }

__global__ void k_zero(){
    size_t st=(size_t)gridDim.x*blockDim.x;
    for(size_t i=(size_t)blockIdx.x*blockDim.x+threadIdx.x; i<CTXN+CNTN; i+=st){
        if(i<CTXN) g_ctx[i]=0.f; else g_cnt[i-CTXN]=0.f;
    }
    if(blockIdx.x==0){
        if(threadIdx.x<Bn) g_umax[threadIdx.x]=0;
        for(int t=threadIdx.x;t<Bn*COn*2;t+=blockDim.x) g_csum[t]=0.f;
    }
}

__global__ void k_prep(const float* __restrict__ uvs, const float* __restrict__ msk,
                       const float* __restrict__ wg, const float* __restrict__ wb,
                       const float* __restrict__ wh){
    int i=blockIdx.x*blockDim.x+threadIdx.x;
    if(i>=Bn*Vn*HWn) return;
    float u=uvs[2*i], v=uvs[2*i+1];
    bool fin=isfinite(u)&&isfinite(v);
    float su=fin?u:0.f, sv=fin?v:0.f;
    int xi=(int)rintf(fminf(fmaxf(su,0.f),1.f)*(float)(An-1));
    int yi=(int)rintf((1.f-fminf(fmaxf(sv,0.f),1.f))*(float)(An-1));
    g_idx[i]=yi*An+xi;
    bool mv=(msk[i]>0.5f)&&fin;
    int bv=i/HWn;
    float w0=fmaxf(wg[bv],0.f), w1=fmaxf(wb[bv],0.f), w2=fmaxf(wh[bv],0.f);
    g_wts[0][i]=(mv&&w0>0.f)?w0:0.f;
    g_wts[1][i]=(mv&&w1>0.f)?w1:0.f;
    g_wts[2][i]=(mv&&w2>0.f)?w2:0.f;
}

__global__ void k_scatter(const float* __restrict__ vf){
    int bv=blockIdx.y;
    int px=blockIdx.x*blockDim.x+threadIdx.x;
    int i=bv*HWn+px;
    int b=bv>>3;
    int idx=g_idx[i];
    float w0=g_wts[0][i], w1=g_wts[1][i], w2=g_wts[2][i];
    if(w0<=0.f && w1<=0.f && w2<=0.f) return;
    float* base=g_ctx+(size_t)b*C3n*Pn+idx;
    const float* vp=vf+(size_t)bv*Cn*HWn+px;
    #pragma unroll 4
    for(int c=0;c<Cn;c++){
        float v=vp[(size_t)c*HWn];
        if(w0>0.f) atomicAdd(base+(size_t)c*Pn, w0*v);
        if(w1>0.f) atomicAdd(base+(size_t)(Cn+c)*Pn, w1*v);
        if(w2>0.f) atomicAdd(base+(size_t)(2*Cn+c)*Pn, w2*v);
    }
    if(w0>0.f) atomicAdd(&g_cnt[((size_t)b*3+0)*Pn+idx], w0);
    if(w1>0.f) atomicAdd(&g_cnt[((size_t)b*3+1)*Pn+idx], w1);
    if(w2>0.f) atomicAdd(&g_cnt[((size_t)b*3+2)*Pn+idx], w2);
}

__global__ void k_finalize(){
    int i=blockIdx.x*blockDim.x+threadIdx.x;
    int b=i>>16, px=i&(Pn-1);
    size_t base=(size_t)b*C3n*Pn+px;
    float c0=g_cnt[((size_t)b*3+0)*Pn+px];
    float c1=g_cnt[((size_t)b*3+1)*Pn+px];
    float c2=g_cnt[((size_t)b*3+2)*Pn+px];
    float i0=1.f/fmaxf(c0,1.f), i1=1.f/fmaxf(c1,1.f), i2=1.f/fmaxf(c2,1.f);
    float ss=0.f;
    #pragma unroll 4
    for(int c=0;c<Cn;c++){
        float g=g_ctx[base+(size_t)c*Pn]*i0;
        float h=g_ctx[base+(size_t)(Cn+c)*Pn]*i1;
        float t=g_ctx[base+(size_t)(2*Cn+c)*Pn]*i2;
        g_ctx[base+(size_t)c*Pn]=g;
        g_ctx[base+(size_t)(Cn+c)*Pn]=h;
        g_ctx[base+(size_t)(2*Cn+c)*Pn]=t;
        float m=(g+h+t)*(1.f/3.f);
        float dg=g-m, dh=h-m, dt=t-m;
        ss+=dg*dg+dh*dh+dt*dt;
    }
    float cov=((c0>0.f?1.f:0.f)+(c1>0.f?1.f:0.f)+(c2>0.f?1.f:0.f))*(1.f/3.f);
    cov=fminf(cov,1.f);
    float uraw=sqrtf(ss*(1.f/(3.f*Cn)));
    g_ctx[base+(size_t)192*Pn]=cov;
    g_uraw[i]=uraw;
    float m=uraw;
    #pragma unroll
    for(int o=16;o>0;o>>=1) m=fmaxf(m,__shfl_xor_sync(0xffffffffu,m,o));
    if((threadIdx.x&31)==0) atomicMax(&g_umax[b], __float_as_int(m));
}

__global__ void k_uncert(float* __restrict__ dout){
    int i=blockIdx.x*blockDim.x+threadIdx.x;
    int b=i>>16, px=i&(Pn-1);
    size_t base=(size_t)b*C3n*Pn+px;
    float cov=g_ctx[base+(size_t)192*Pn];
    float sc=fmaxf(__int_as_float(g_umax[b]),1e-6f);
    float un=fminf(fmaxf(g_uraw[i]/sc,0.f),1.f)*cov;
    g_ctx[base+(size_t)193*Pn]=un;
    dout[OFF_COV+i]=cov;
    dout[OFF_UNC+i]=un;
}

__global__ void k_conf(const float* __restrict__ cw, const float* __restrict__ cb,
                       float* __restrict__ dout){
    __shared__ float s_cw[3*C3n];
    for(int l=threadIdx.x;l<3*C3n;l+=blockDim.x) s_cw[l]=cw[l];
    __syncthreads();
    int i=blockIdx.x*blockDim.x+threadIdx.x;
    int b=i>>16, px=i&(Pn-1);
    const float* xp=g_ctx+(size_t)b*C3n*Pn+px;
    float a0=cb[0], a1=cb[1], a2=cb[2];
    #pragma unroll 2
    for(int ci=0;ci<C3n;ci++){
        float x=xp[(size_t)ci*Pn];
        a0+=x*s_cw[ci]; a1+=x*s_cw[C3n+ci]; a2+=x*s_cw[2*C3n+ci];
    }
    dout[OFF_CONF+((size_t)(b*3+0))*Pn+px]=sigf(a0);
    dout[OFF_CONF+((size_t)(b*3+1))*Pn+px]=sigf(a1);
    dout[OFF_CONF+((size_t)(b*3+2))*Pn+px]=sigf(a2);
}

// weights -> blocked layout [coT(3)][ci(CINP)][tap(9)][co64]
template<int MODE>
__global__ void k_wtrans(const float* __restrict__ w){
    constexpr int CIN =(MODE==0)?C3n:COn;
    constexpr int CINP=(MODE==0)?CIN1P:COn;
    int n=3*CINP*9*64;
    int i=blockIdx.x*blockDim.x+threadIdx.x;
    if(i>=n) return;
    int coT=i/(CINP*576);
    int r=i-coT*(CINP*576);
    int ci=r/576;
    int r2=r-ci*576;
    int tap=r2>>6, cl=r2&63;
    int co=coT*64+cl;
    float v=(ci<CIN)?w[((size_t)co*CIN+ci)*9+tap]:0.f;
    if(MODE==0) g_wT1[i]=v; else g_wT2[i]=v;
}

// 3x3 conv: f32x2 FMA, 16x16 px x 64 co per block, reg-staged fills,
// fused per-channel sum/sumsq epilogue.
template<int CIN,int CINP,int NCH,int MODE>
__global__ void __launch_bounds__(256,1) k_conv(const float* __restrict__ bias){
    __shared__ __align__(16) float s_in[8*344];   // 8 ci planes, 18 rows * 19 pitch
    __shared__ __align__(16) float s_w[4608];     // [ci8][tap9][co64]
    const float* in=(MODE==0)?g_ctx:g_h1;
    const float* wT=(MODE==0)?g_wT1:g_wT2;
    float* out     =(MODE==0)?g_h1 :g_h2;

    const int tid=threadIdx.x;
    const int cg=tid>>5, lane=tid&31;
    const int prow=lane>>1, pxo=(lane&1)*8;
    const int tx=(blockIdx.x&15)*16, ty=(blockIdx.x>>4)*16;
    const int coT=blockIdx.y, b=blockIdx.z;
    const float* inB=in+(size_t)b*CIN*Pn;
    const float* wB=wT+(size_t)coT*CINP*576;

    // precompute staging coords once (div-free inner loop)
    int goff[11], soff[11]; bool ok[11], sv[11];
    #pragma unroll
    for(int k=0;k<11;k++){
        int e=lane+k*32;
        int y=e/18, x=e-y*18;
        int gy=ty-1+y, gx=tx-1+x;
        sv[k]=(e<324);
        ok[k]=sv[k]&&(gy>=0)&&(gy<An)&&(gx>=0)&&(gx<An);
        goff[k]=ok[k]?(gy*An+gx):0;
        soff[k]=cg*344+y*19+x;
    }

    ull acc[8][4];
    #pragma unroll
    for(int p=0;p<8;p++){ acc[p][0]=0; acc[p][1]=0; acc[p][2]=0; acc[p][3]=0; }

    float   vstg[11];
    float4  wstg[5];

    // stage ch 0
    {
        int ci=cg; if(MODE==0) ci=min(ci,CIN-1);
        const float* src=inB+(size_t)ci*Pn;
        #pragma unroll
        for(int k=0;k<11;k++) vstg[k]=ok[k]?src[goff[k]]:0.f;
        const float4* wsrc=reinterpret_cast<const float4*>(wB);
        #pragma unroll
        for(int k=0;k<4;k++) wstg[k]=wsrc[tid+k*256];
        if(tid<128) wstg[4]=wsrc[tid+1024];
    }

    #pragma unroll 1
    for(int ch=0;ch<NCH;ch++){
        if(ch>0) __syncthreads();
        // commit staged data
        #pragma unroll
        for(int k=0;k<11;k++) if(sv[k]) s_in[soff[k]]=vstg[k];
        float4* wd=reinterpret_cast<float4*>(s_w);
        #pragma unroll
        for(int k=0;k<4;k++) wd[tid+k*256]=wstg[k];
        if(tid<128) wd[tid+1024]=wstg[4];
        __syncthreads();

        // stage next chunk (overlaps with compute)
        if(ch+1<NCH){
            int ci=(ch+1)*8+cg; if(MODE==0) ci=min(ci,CIN-1);
            const float* src=inB+(size_t)ci*Pn;
            #pragma unroll
            for(int k=0;k<11;k++) vstg[k]=ok[k]?src[goff[k]]:0.f;
            const float4* wsrc=reinterpret_cast<const float4*>(wB+(size_t)(ch+1)*4608);
            #pragma unroll
            for(int k=0;k<4;k++) wstg[k]=wsrc[tid+k*256];
            if(tid<128) wstg[4]=wsrc[tid+1024];
        }

        // compute
        #pragma unroll 2
        for(int ci=0;ci<8;ci++){
            #pragma unroll
            for(int kh=0;kh<3;kh++){
                const float* row=s_in+ci*344+(prow+kh)*19+pxo;
                ull rd[10];
                #pragma unroll
                for(int k=0;k<10;k++) rd[k]=pack2(row[k]);
                #pragma unroll
                for(int kw=0;kw<3;kw++){
                    const ull* wp=reinterpret_cast<const ull*>(s_w+(ci*9+kh*3+kw)*64+cg*8);
                    ull w0=wp[0], w1=wp[1], w2=wp[2], w3=wp[3];
                    #pragma unroll
                    for(int p=0;p<8;p++){
                        fma2(acc[p][0], rd[p+kw], w0);
                        fma2(acc[p][1], rd[p+kw], w1);
                        fma2(acc[p][2], rd[p+kw], w2);
                        fma2(acc[p][3], rd[p+kw], w3);
                    }
                }
            }
        }
    }

    // epilogue: bias, store, fused channel sum/sumsq
    const int ybase=ty+prow, xbase=tx+pxo;
    #pragma unroll
    for(int oc=0;oc<8;oc++){
        int co=coT*64+cg*8+oc;
        float bv=__ldg(bias+co);
        float vals[8]; float s=0.f,q=0.f;
        #pragma unroll
        for(int p=0;p<8;p++){
            float lo,hi; unpack2(acc[p][oc>>1],lo,hi);
            float v=((oc&1)?hi:lo)+bv;
            vals[p]=v; s+=v; q+=v*v;
        }
        float* op=out+((size_t)(b*COn+co)*An+ybase)*An+xbase;
        reinterpret_cast<float4*>(op)[0]=make_float4(vals[0],vals[1],vals[2],vals[3]);
        reinterpret_cast<float4*>(op)[1]=make_float4(vals[4],vals[5],vals[6],vals[7]);
        #pragma unroll
        for(int o=16;o>0;o>>=1){
            s+=__shfl_xor_sync(0xffffffffu,s,o);
            q+=__shfl_xor_sync(0xffffffffu,q,o);
        }
        if(lane==0){
            atomicAdd(&g_csum[(b*COn+co)*2],s);
            atomicAdd(&g_csum[(b*COn+co)*2+1],q);
        }
    }
}

// group stats -> per-channel affine; re-zero g_csum for next accumulation
__global__ void k_stats(const float* __restrict__ scale, const float* __restrict__ shift){
    __shared__ float gm[16], gr[16];
    int t=threadIdx.x;
    if(t<Bn*8){
        int b=t/8, g=t%8;
        float s=0.f, q=0.f;
        for(int c=0;c<24;c++){
            s+=g_csum[(b*COn+g*24+c)*2];
            q+=g_csum[(b*COn+g*24+c)*2+1];
        }
        float N=24.f*(float)Pn;
        float mean=s/N;
        float var=q/N-mean*mean;
        gm[t]=mean;
        gr[t]=rsqrtf(var+1e-5f);
    }
    __syncthreads();
    if(t<Bn*COn){
        int b=t/COn, c=t%COn, g=c/24;
        float a=gr[b*8+g]*scale[c];
        g_sA[t]=a;
        g_sB[t]=shift[c]-gm[b*8+g]*a;
        g_csum[t*2]=0.f; g_csum[t*2+1]=0.f;
    }
}

// GN apply + SiLU in place; MODE==1 also accumulates post-silu sums (for gate)
template<int MODE>
__global__ void k_apply(){
    float* x=(MODE==0)?g_h1:g_h2;
    int i=blockIdx.x*blockDim.x+threadIdx.x;
    int bc=i>>16;
    float v=x[i]*g_sA[bc]+g_sB[bc];
    float r=siluf(v);
    x[i]=r;
    if(MODE==1){
        float s=r;
        #pragma unroll
        for(int o=16;o>0;o>>=1) s+=__shfl_xor_sync(0xffffffffu,s,o);
        __shared__ float aS[8];
        int w=threadIdx.x>>5;
        if((threadIdx.x&31)==0) aS[w]=s;
        __syncthreads();
        if(threadIdx.x==0){
            float S=0.f;
            #pragma unroll
            for(int k=0;k<8;k++) S+=aS[k];
            atomicAdd(&g_csum[bc*2],S);
        }
    }
}

__global__ void k_gate(const float* __restrict__ gw1, const float* __restrict__ gb1,
                       const float* __restrict__ gw2, const float* __restrict__ gb2){
    __shared__ float pooled[COn];
    __shared__ float hbuf[HIDn];
    for(int b=0;b<Bn;b++){
        for(int c=threadIdx.x;c<COn;c+=blockDim.x)
            pooled[c]=g_csum[(b*COn+c)*2]*(1.f/(float)Pn);
        __syncthreads();
        if(threadIdx.x<HIDn){
            float s=gb1[threadIdx.x];
            for(int c=0;c<COn;c++) s+=gw1[threadIdx.x*COn+c]*pooled[c];
            hbuf[threadIdx.x]=siluf(s);
        }
        __syncthreads();
        if(threadIdx.x<COn){
            float s=gb2[threadIdx.x];
            for(int j=0;j<HIDn;j++) s+=gw2[threadIdx.x*HIDn+j]*hbuf[j];
            g_gate[b*COn+threadIdx.x]=0.5f+sigf(s);
        }
        __syncthreads();
    }
}

__global__ void __launch_bounds__(256) k_res_combine(
    const float* __restrict__ rpw, const float* __restrict__ rpb,
    const float* __restrict__ prs, const float* __restrict__ pmix,
    float* __restrict__ dout){
    __shared__ __align__(16) float s_w[97*64];
    const int br=blockIdx.y, b=blockIdx.z;
    const int og=threadIdx.x>>6, pl=threadIdx.x&63;
    const int pxb=blockIdx.x*256;
    const float* ctxb=g_ctx+(size_t)b*C3n*Pn;

    ull acc[4][8];
    #pragma unroll
    for(int k=0;k<4;k++)
        #pragma unroll
        for(int j=0;j<8;j++) acc[k][j]=0;

    #pragma unroll 1
    for(int half=0;half<2;half++){
        int ci0=half*97;
        for(int l=threadIdx.x;l<97*64;l+=256){
            int ci=l>>6, o=l&63;
            s_w[l]=rpw[(size_t)(br*64+o)*C3n+ci0+ci];
        }
        __syncthreads();
        #pragma unroll 1
        for(int ci=0;ci<97;ci++){
            const float* xp=ctxb+(size_t)(ci0+ci)*Pn+pxb+pl;
            ull p0=pack2(xp[0]), p1=pack2(xp[64]), p2=pack2(xp[128]), p3=pack2(xp[192]);
            const ull* wrow=reinterpret_cast<const ull*>(s_w+ci*64+og*16);
            #pragma unroll
            for(int j=0;j<8;j++){
                ull w=wrow[j];
                fma2(acc[0][j],p0,w); fma2(acc[1][j],p1,w);
                fma2(acc[2][j],p2,w); fma2(acc[3][j],p3,w);
            }
        }
        __syncthreads();
    }

    const float trs=tanhf(prs[0]);
    const float ms=tanhf(pmix[0]);
    #pragma unroll
    for(int k=0;k<4;k++){
        int px=pxb+pl+k*64;
        float confv=dout[OFF_CONF+((size_t)(b*3+br))*Pn+px];
        #pragma unroll
        for(int j=0;j<8;j++){
            float lo,hi; unpack2(acc[k][j],lo,hi);
            #pragma unroll
            for(int half=0;half<2;half++){
                int c=og*16+2*j+half;
                int co=br*64+c;
                float res=(half?hi:lo)+rpb[co];
                float h=g_h2[((size_t)(b*COn)+co)*Pn+px];
                float refine=h*g_gate[b*COn+co]+trs*res;
                float feat=ctxb[(size_t)co*Pn+px];
                dout[(size_t)br*((size_t)Bn*Cn*Pn)+((size_t)(b*Cn+c))*Pn+px]
                    =feat+ms*refine*confv;
            }
        }
    }
}

extern "C" void kernel_launch(void* const* d_in, const int* in_sizes, int n_in,
                              void* d_out, int out_size){
    const float* vf   =(const float*)d_in[0];
    const float* uvs  =(const float*)d_in[1];
    const float* msk  =(const float*)d_in[2];
    const float* wg   =(const float*)d_in[3];
    const float* wb   =(const float*)d_in[4];
    const float* wh   =(const float*)d_in[5];
    const float* c1w  =(const float*)d_in[7];
    const float* c1b  =(const float*)d_in[8];
    const float* g1s  =(const float*)d_in[9];
    const float* g1b  =(const float*)d_in[10];
    const float* c2w  =(const float*)d_in[11];
    const float* c2b  =(const float*)d_in[12];
    const float* g2s  =(const float*)d_in[13];
    const float* g2b  =(const float*)d_in[14];
    const float* gw1  =(const float*)d_in[15];
    const float* gb1  =(const float*)d_in[16];
    const float* gw2  =(const float*)d_in[17];
    const float* gb2  =(const float*)d_in[18];
    const float* rpw  =(const float*)d_in[19];
    const float* rpb  =(const float*)d_in[20];
    const float* rs   =(const float*)d_in[21];
    const float* cfw  =(const float*)d_in[22];
    const float* cfb  =(const float*)d_in[23];
    const float* mixs =(const float*)d_in[24];
    float* dout=(float*)d_out;

    k_zero<<<512,256>>>();                                        // 0
    k_prep<<<1024,256>>>(uvs,msk,wg,wb,wh);                       // 1
    k_wtrans<0><<<(3*CIN1P*9*64+255)/256,256>>>(c1w);             // 2
    k_scatter<<<dim3(64,16),256>>>(vf);                           // 3 (profiled slot)
    k_wtrans<1><<<(3*COn*9*64+255)/256,256>>>(c2w);               // 4
    k_finalize<<<512,256>>>();                                    // 5
    k_uncert<<<512,256>>>(dout);                                  // 6
    k_conf<<<512,256>>>(cfw,cfb,dout);                            // 7
    k_conv<C3n,CIN1P,25,0><<<dim3(256,3,2),256>>>(c1b);           // 8
    k_stats<<<1,384>>>(g1s,g1b);                                  // 9
    k_apply<0><<<98304,256>>>();                                  // 10
    k_conv<COn,COn,24,1><<<dim3(256,3,2),256>>>(c2b);             // 11
    k_stats<<<1,384>>>(g2s,g2b);                                  // 12
    k_apply<1><<<98304,256>>>();                                  // 13
    k_gate<<<1,192>>>(gw1,gb1,gw2,gb2);                           // 14
    k_res_combine<<<dim3(256,3,2),256>>>(rpw,rpb,rs,mixs,dout);   // 15
}

// round 4
// speedup vs baseline: 1.4029x; 1.0030x over previous
#include <cuda_runtime.h>
#include <math.h>
#include <stdint.h>

typedef unsigned long long ull;

constexpr int Bn=2, Vn=8, Cn=64, An=256;
constexpr int HWn=128*128, Pn=An*An;
constexpr int C3n=194, COn=192, HIDn=48, CIN1P=200;

constexpr size_t CTXN=(size_t)Bn*C3n*Pn;
constexpr size_t CNTN=(size_t)Bn*3*Pn;
constexpr size_t OFF_COV =(size_t)3*Bn*Cn*Pn;
constexpr size_t OFF_UNC =OFF_COV+(size_t)Bn*Pn;
constexpr size_t OFF_CONF=OFF_UNC+(size_t)Bn*Pn;

__device__ float  g_ctx[CTXN];
__device__ float  g_cnt[CNTN];
__device__ float  g_uraw[(size_t)Bn*Pn];
__device__ int    g_umax[Bn];
__device__ int    g_idx[Bn*Vn*HWn];
__device__ float  g_wts[3][Bn*Vn*HWn];
__device__ float  g_h1[(size_t)Bn*COn*Pn];
__device__ float  g_h2[(size_t)Bn*COn*Pn];
__device__ float  g_wT1[3*CIN1P*9*64];
__device__ float  g_wT2[3*COn*9*64];
__device__ float  g_csum[Bn*COn*2];
__device__ float  g_sA[Bn*COn], g_sB[Bn*COn];
__device__ float  g_gate[Bn*COn];

__device__ __forceinline__ float siluf(float x){ return x/(1.f+__expf(-x)); }
__device__ __forceinline__ float sigf(float x){ return 1.f/(1.f+__expf(-x)); }
__device__ __forceinline__ ull pack2(float v){ ull r; asm("mov.b64 %0,{%1,%1};":"=l"(r):"f"(v)); return r; }
__device__ __forceinline__ void fma2(ull&a, ull x, ull w){ asm("fma.rn.f32x2 %0,%1,%2,%0;":"+l"(a):"l"(x),"l"(w)); }
__device__ __forceinline__ void unpack2(ull v, float&lo, float&hi){ asm("mov.b64 {%0,%1},%2;":"=f"(lo),"=f"(hi):"l"(v)); }

__global__ void k_zero(){
    size_t st=(size_t)gridDim.x*blockDim.x;
    for(size_t i=(size_t)blockIdx.x*blockDim.x+threadIdx.x; i<CTXN+CNTN; i+=st){
        if(i<CTXN) g_ctx[i]=0.f; else g_cnt[i-CTXN]=0.f;
    }
    if(blockIdx.x==0){
        if(threadIdx.x<Bn) g_umax[threadIdx.x]=0;
        for(int t=threadIdx.x;t<Bn*COn*2;t+=blockDim.x) g_csum[t]=0.f;
    }
}

__global__ void k_prep(const float* __restrict__ uvs, const float* __restrict__ msk,
                       const float* __restrict__ wg, const float* __restrict__ wb,
                       const float* __restrict__ wh){
    int i=blockIdx.x*blockDim.x+threadIdx.x;
    if(i>=Bn*Vn*HWn) return;
    float u=uvs[2*i], v=uvs[2*i+1];
    bool fin=isfinite(u)&&isfinite(v);
    float su=fin?u:0.f, sv=fin?v:0.f;
    int xi=(int)rintf(fminf(fmaxf(su,0.f),1.f)*(float)(An-1));
    int yi=(int)rintf((1.f-fminf(fmaxf(sv,0.f),1.f))*(float)(An-1));
    g_idx[i]=yi*An+xi;
    bool mv=(msk[i]>0.5f)&&fin;
    int bv=i/HWn;
    float w0=fmaxf(wg[bv],0.f), w1=fmaxf(wb[bv],0.f), w2=fmaxf(wh[bv],0.f);
    g_wts[0][i]=(mv&&w0>0.f)?w0:0.f;
    g_wts[1][i]=(mv&&w1>0.f)?w1:0.f;
    g_wts[2][i]=(mv&&w2>0.f)?w2:0.f;
}

__global__ void k_scatter(const float* __restrict__ vf){
    int bv=blockIdx.y;
    int px=blockIdx.x*blockDim.x+threadIdx.x;
    int i=bv*HWn+px;
    int b=bv>>3;
    int idx=g_idx[i];
    float w0=g_wts[0][i], w1=g_wts[1][i], w2=g_wts[2][i];
    if(w0<=0.f && w1<=0.f && w2<=0.f) return;
    float* base=g_ctx+(size_t)b*C3n*Pn+idx;
    const float* vp=vf+(size_t)bv*Cn*HWn+px;
    #pragma unroll 4
    for(int c=0;c<Cn;c++){
        float v=vp[(size_t)c*HWn];
        if(w0>0.f) atomicAdd(base+(size_t)c*Pn, w0*v);
        if(w1>0.f) atomicAdd(base+(size_t)(Cn+c)*Pn, w1*v);
        if(w2>0.f) atomicAdd(base+(size_t)(2*Cn+c)*Pn, w2*v);
    }
    if(w0>0.f) atomicAdd(&g_cnt[((size_t)b*3+0)*Pn+idx], w0);
    if(w1>0.f) atomicAdd(&g_cnt[((size_t)b*3+1)*Pn+idx], w1);
    if(w2>0.f) atomicAdd(&g_cnt[((size_t)b*3+2)*Pn+idx], w2);
}

__global__ void k_finalize(){
    int i=blockIdx.x*blockDim.x+threadIdx.x;
    int b=i>>16, px=i&(Pn-1);
    size_t base=(size_t)b*C3n*Pn+px;
    float c0=g_cnt[((size_t)b*3+0)*Pn+px];
    float c1=g_cnt[((size_t)b*3+1)*Pn+px];
    float c2=g_cnt[((size_t)b*3+2)*Pn+px];
    float i0=1.f/fmaxf(c0,1.f), i1=1.f/fmaxf(c1,1.f), i2=1.f/fmaxf(c2,1.f);
    float ss=0.f;
    #pragma unroll 4
    for(int c=0;c<Cn;c++){
        float g=g_ctx[base+(size_t)c*Pn]*i0;
        float h=g_ctx[base+(size_t)(Cn+c)*Pn]*i1;
        float t=g_ctx[base+(size_t)(2*Cn+c)*Pn]*i2;
        g_ctx[base+(size_t)c*Pn]=g;
        g_ctx[base+(size_t)(Cn+c)*Pn]=h;
        g_ctx[base+(size_t)(2*Cn+c)*Pn]=t;
        float m=(g+h+t)*(1.f/3.f);
        float dg=g-m, dh=h-m, dt=t-m;
        ss+=dg*dg+dh*dh+dt*dt;
    }
    float cov=((c0>0.f?1.f:0.f)+(c1>0.f?1.f:0.f)+(c2>0.f?1.f:0.f))*(1.f/3.f);
    cov=fminf(cov,1.f);
    float uraw=sqrtf(ss*(1.f/(3.f*Cn)));
    g_ctx[base+(size_t)192*Pn]=cov;
    g_uraw[i]=uraw;
    float m=uraw;
    #pragma unroll
    for(int o=16;o>0;o>>=1) m=fmaxf(m,__shfl_xor_sync(0xffffffffu,m,o));
    if((threadIdx.x&31)==0) atomicMax(&g_umax[b], __float_as_int(m));
}

__global__ void k_uncert(float* __restrict__ dout){
    int i=blockIdx.x*blockDim.x+threadIdx.x;
    int b=i>>16, px=i&(Pn-1);
    size_t base=(size_t)b*C3n*Pn+px;
    float cov=g_ctx[base+(size_t)192*Pn];
    float sc=fmaxf(__int_as_float(g_umax[b]),1e-6f);
    float un=fminf(fmaxf(g_uraw[i]/sc,0.f),1.f)*cov;
    g_ctx[base+(size_t)193*Pn]=un;
    dout[OFF_COV+i]=cov;
    dout[OFF_UNC+i]=un;
}

__global__ void k_conf(const float* __restrict__ cw, const float* __restrict__ cb,
                       float* __restrict__ dout){
    __shared__ float s_cw[3*C3n];
    for(int l=threadIdx.x;l<3*C3n;l+=blockDim.x) s_cw[l]=cw[l];
    __syncthreads();
    int i=blockIdx.x*blockDim.x+threadIdx.x;
    int b=i>>16, px=i&(Pn-1);
    const float* xp=g_ctx+(size_t)b*C3n*Pn+px;
    float a0=cb[0], a1=cb[1], a2=cb[2];
    #pragma unroll 2
    for(int ci=0;ci<C3n;ci++){
        float x=xp[(size_t)ci*Pn];
        a0+=x*s_cw[ci]; a1+=x*s_cw[C3n+ci]; a2+=x*s_cw[2*C3n+ci];
    }
    dout[OFF_CONF+((size_t)(b*3+0))*Pn+px]=sigf(a0);
    dout[OFF_CONF+((size_t)(b*3+1))*Pn+px]=sigf(a1);
    dout[OFF_CONF+((size_t)(b*3+2))*Pn+px]=sigf(a2);
}

// weights -> blocked layout [coT(3)][ci(CINP)][tap(9)][co64]
template<int MODE>
__global__ void k_wtrans(const float* __restrict__ w){
    constexpr int CIN =(MODE==0)?C3n:COn;
    constexpr int CINP=(MODE==0)?CIN1P:COn;
    int n=3*CINP*9*64;
    int i=blockIdx.x*blockDim.x+threadIdx.x;
    if(i>=n) return;
    int coT=i/(CINP*576);
    int r=i-coT*(CINP*576);
    int ci=r/576;
    int r2=r-ci*576;
    int tap=r2>>6, cl=r2&63;
    int co=coT*64+cl;
    float v=(ci<CIN)?w[((size_t)co*CIN+ci)*9+tap]:0.f;
    if(MODE==0) g_wT1[i]=v; else g_wT2[i]=v;
}

// 3x3 conv: f32x2 FMA, 16x16 px x 64 co per block, reg-staged fills,
// fused per-channel sum/sumsq epilogue.
template<int CIN,int CINP,int NCH,int MODE>
__global__ void __launch_bounds__(256,1) k_conv(const float* __restrict__ bias){
    __shared__ __align__(16) float s_in[8*344];   // 8 ci planes, 18 rows * 19 pitch
    __shared__ __align__(16) float s_w[4608];     // [ci8][tap9][co64]
    const float* in=(MODE==0)?g_ctx:g_h1;
    const float* wT=(MODE==0)?g_wT1:g_wT2;
    float* out     =(MODE==0)?g_h1 :g_h2;

    const int tid=threadIdx.x;
    const int cg=tid>>5, lane=tid&31;
    const int prow=lane>>1, pxo=(lane&1)*8;
    const int tx=(blockIdx.x&15)*16, ty=(blockIdx.x>>4)*16;
    const int coT=blockIdx.y, b=blockIdx.z;
    const float* inB=in+(size_t)b*CIN*Pn;
    const float* wB=wT+(size_t)coT*CINP*576;

    // precompute staging coords once (div-free inner loop)
    int goff[11], soff[11]; bool ok[11], sv[11];
    #pragma unroll
    for(int k=0;k<11;k++){
        int e=lane+k*32;
        int y=e/18, x=e-y*18;
        int gy=ty-1+y, gx=tx-1+x;
        sv[k]=(e<324);
        ok[k]=sv[k]&&(gy>=0)&&(gy<An)&&(gx>=0)&&(gx<An);
        goff[k]=ok[k]?(gy*An+gx):0;
        soff[k]=cg*344+y*19+x;
    }

    ull acc[8][4];
    #pragma unroll
    for(int p=0;p<8;p++){ acc[p][0]=0; acc[p][1]=0; acc[p][2]=0; acc[p][3]=0; }

    float   vstg[11];
    float4  wstg[5];

    // stage ch 0
    {
        int ci=cg; if(MODE==0) ci=min(ci,CIN-1);
        const float* src=inB+(size_t)ci*Pn;
        #pragma unroll
        for(int k=0;k<11;k++) vstg[k]=ok[k]?src[goff[k]]:0.f;
        const float4* wsrc=reinterpret_cast<const float4*>(wB);
        #pragma unroll
        for(int k=0;k<4;k++) wstg[k]=wsrc[tid+k*256];
        if(tid<128) wstg[4]=wsrc[tid+1024];
    }

    #pragma unroll 1
    for(int ch=0;ch<NCH;ch++){
        if(ch>0) __syncthreads();
        // commit staged data
        #pragma unroll
        for(int k=0;k<11;k++) if(sv[k]) s_in[soff[k]]=vstg[k];
        float4* wd=reinterpret_cast<float4*>(s_w);
        #pragma unroll
        for(int k=0;k<4;k++) wd[tid+k*256]=wstg[k];
        if(tid<128) wd[tid+1024]=wstg[4];
        __syncthreads();

        // stage next chunk (overlaps with compute)
        if(ch+1<NCH){
            int ci=(ch+1)*8+cg; if(MODE==0) ci=min(ci,CIN-1);
            const float* src=inB+(size_t)ci*Pn;
            #pragma unroll
            for(int k=0;k<11;k++) vstg[k]=ok[k]?src[goff[k]]:0.f;
            const float4* wsrc=reinterpret_cast<const float4*>(wB+(size_t)(ch+1)*4608);
            #pragma unroll
            for(int k=0;k<4;k++) wstg[k]=wsrc[tid+k*256];
            if(tid<128) wstg[4]=wsrc[tid+1024];
        }

        // compute
        #pragma unroll 2
        for(int ci=0;ci<8;ci++){
            #pragma unroll
            for(int kh=0;kh<3;kh++){
                const float* row=s_in+ci*344+(prow+kh)*19+pxo;
                ull rd[10];
                #pragma unroll
                for(int k=0;k<10;k++) rd[k]=pack2(row[k]);
                #pragma unroll
                for(int kw=0;kw<3;kw++){
                    const ull* wp=reinterpret_cast<const ull*>(s_w+(ci*9+kh*3+kw)*64+cg*8);
                    ull w0=wp[0], w1=wp[1], w2=wp[2], w3=wp[3];
                    #pragma unroll
                    for(int p=0;p<8;p++){
                        fma2(acc[p][0], rd[p+kw], w0);
                        fma2(acc[p][1], rd[p+kw], w1);
                        fma2(acc[p][2], rd[p+kw], w2);
                        fma2(acc[p][3], rd[p+kw], w3);
                    }
                }
            }
        }
    }

    // epilogue: bias, store, fused channel sum/sumsq
    const int ybase=ty+prow, xbase=tx+pxo;
    #pragma unroll
    for(int oc=0;oc<8;oc++){
        int co=coT*64+cg*8+oc;
        float bv=__ldg(bias+co);
        float vals[8]; float s=0.f,q=0.f;
        #pragma unroll
        for(int p=0;p<8;p++){
            float lo,hi; unpack2(acc[p][oc>>1],lo,hi);
            float v=((oc&1)?hi:lo)+bv;
            vals[p]=v; s+=v; q+=v*v;
        }
        float* op=out+((size_t)(b*COn+co)*An+ybase)*An+xbase;
        reinterpret_cast<float4*>(op)[0]=make_float4(vals[0],vals[1],vals[2],vals[3]);
        reinterpret_cast<float4*>(op)[1]=make_float4(vals[4],vals[5],vals[6],vals[7]);
        #pragma unroll
        for(int o=16;o>0;o>>=1){
            s+=__shfl_xor_sync(0xffffffffu,s,o);
            q+=__shfl_xor_sync(0xffffffffu,q,o);
        }
        if(lane==0){
            atomicAdd(&g_csum[(b*COn+co)*2],s);
            atomicAdd(&g_csum[(b*COn+co)*2+1],q);
        }
    }
}

// group stats -> per-channel affine; re-zero g_csum for next accumulation
__global__ void k_stats(const float* __restrict__ scale, const float* __restrict__ shift){
    __shared__ float gm[16], gr[16];
    int t=threadIdx.x;
    if(t<Bn*8){
        int b=t/8, g=t%8;
        float s=0.f, q=0.f;
        for(int c=0;c<24;c++){
            s+=g_csum[(b*COn+g*24+c)*2];
            q+=g_csum[(b*COn+g*24+c)*2+1];
        }
        float N=24.f*(float)Pn;
        float mean=s/N;
        float var=q/N-mean*mean;
        gm[t]=mean;
        gr[t]=rsqrtf(var+1e-5f);
    }
    __syncthreads();
    if(t<Bn*COn){
        int b=t/COn, c=t%COn, g=c/24;
        float a=gr[b*8+g]*scale[c];
        g_sA[t]=a;
        g_sB[t]=shift[c]-gm[b*8+g]*a;
        g_csum[t*2]=0.f; g_csum[t*2+1]=0.f;
    }
}

// GN apply + SiLU in place; MODE==1 also accumulates post-silu sums (for gate)
template<int MODE>
__global__ void k_apply(){
    float* x=(MODE==0)?g_h1:g_h2;
    int i=blockIdx.x*blockDim.x+threadIdx.x;
    int bc=i>>16;
    float v=x[i]*g_sA[bc]+g_sB[bc];
    float r=siluf(v);
    x[i]=r;
    if(MODE==1){
        float s=r;
        #pragma unroll
        for(int o=16;o>0;o>>=1) s+=__shfl_xor_sync(0xffffffffu,s,o);
        __shared__ float aS[8];
        int w=threadIdx.x>>5;
        if((threadIdx.x&31)==0) aS[w]=s;
        __syncthreads();
        if(threadIdx.x==0){
            float S=0.f;
            #pragma unroll
            for(int k=0;k<8;k++) S+=aS[k];
            atomicAdd(&g_csum[bc*2],S);
        }
    }
}

__global__ void k_gate(const float* __restrict__ gw1, const float* __restrict__ gb1,
                       const float* __restrict__ gw2, const float* __restrict__ gb2){
    __shared__ float pooled[COn];
    __shared__ float hbuf[HIDn];
    for(int b=0;b<Bn;b++){
        for(int c=threadIdx.x;c<COn;c+=blockDim.x)
            pooled[c]=g_csum[(b*COn+c)*2]*(1.f/(float)Pn);
        __syncthreads();
        if(threadIdx.x<HIDn){
            float s=gb1[threadIdx.x];
            for(int c=0;c<COn;c++) s+=gw1[threadIdx.x*COn+c]*pooled[c];
            hbuf[threadIdx.x]=siluf(s);
        }
        __syncthreads();
        if(threadIdx.x<COn){
            float s=gb2[threadIdx.x];
            for(int j=0;j<HIDn;j++) s+=gw2[threadIdx.x*HIDn+j]*hbuf[j];
            g_gate[b*COn+threadIdx.x]=0.5f+sigf(s);
        }
        __syncthreads();
    }
}

__global__ void __launch_bounds__(256) k_res_combine(
    const float* __restrict__ rpw, const float* __restrict__ rpb,
    const float* __restrict__ prs, const float* __restrict__ pmix,
    float* __restrict__ dout){
    __shared__ __align__(16) float s_w[97*64];
    const int br=blockIdx.y, b=blockIdx.z;
    const int og=threadIdx.x>>6, pl=threadIdx.x&63;
    const int pxb=blockIdx.x*256;
    const float* ctxb=g_ctx+(size_t)b*C3n*Pn;

    ull acc[4][8];
    #pragma unroll
    for(int k=0;k<4;k++)
        #pragma unroll
        for(int j=0;j<8;j++) acc[k][j]=0;

    #pragma unroll 1
    for(int half=0;half<2;half++){
        int ci0=half*97;
        for(int l=threadIdx.x;l<97*64;l+=256){
            int ci=l>>6, o=l&63;
            s_w[l]=rpw[(size_t)(br*64+o)*C3n+ci0+ci];
        }
        __syncthreads();
        #pragma unroll 1
        for(int ci=0;ci<97;ci++){
            const float* xp=ctxb+(size_t)(ci0+ci)*Pn+pxb+pl;
            ull p0=pack2(xp[0]), p1=pack2(xp[64]), p2=pack2(xp[128]), p3=pack2(xp[192]);
            const ull* wrow=reinterpret_cast<const ull*>(s_w+ci*64+og*16);
            #pragma unroll
            for(int j=0;j<8;j++){
                ull w=wrow[j];
                fma2(acc[0][j],p0,w); fma2(acc[1][j],p1,w);
                fma2(acc[2][j],p2,w); fma2(acc[3][j],p3,w);
            }
        }
        __syncthreads();
    }

    const float trs=tanhf(prs[0]);
    const float ms=tanhf(pmix[0]);
    #pragma unroll
    for(int k=0;k<4;k++){
        int px=pxb+pl+k*64;
        float confv=dout[OFF_CONF+((size_t)(b*3+br))*Pn+px];
        #pragma unroll
        for(int j=0;j<8;j++){
            float lo,hi; unpack2(acc[k][j],lo,hi);
            #pragma unroll
            for(int half=0;half<2;half++){
                int c=og*16+2*j+half;
                int co=br*64+c;
                float res=(half?hi:lo)+rpb[co];
                float h=g_h2[((size_t)(b*COn)+co)*Pn+px];
                float refine=h*g_gate[b*COn+co]+trs*res;
                float feat=ctxb[(size_t)co*Pn+px];
                dout[(size_t)br*((size_t)Bn*Cn*Pn)+((size_t)(b*Cn+c))*Pn+px]
                    =feat+ms*refine*confv;
            }
        }
    }
}

extern "C" void kernel_launch(void* const* d_in, const int* in_sizes, int n_in,
                              void* d_out, int out_size){
    const float* vf   =(const float*)d_in[0];
    const float* uvs  =(const float*)d_in[1];
    const float* msk  =(const float*)d_in[2];
    const float* wg   =(const float*)d_in[3];
    const float* wb   =(const float*)d_in[4];
    const float* wh   =(const float*)d_in[5];
    const float* c1w  =(const float*)d_in[7];
    const float* c1b  =(const float*)d_in[8];
    const float* g1s  =(const float*)d_in[9];
    const float* g1b  =(const float*)d_in[10];
    const float* c2w  =(const float*)d_in[11];
    const float* c2b  =(const float*)d_in[12];
    const float* g2s  =(const float*)d_in[13];
    const float* g2b  =(const float*)d_in[14];
    const float* gw1  =(const float*)d_in[15];
    const float* gb1  =(const float*)d_in[16];
    const float* gw2  =(const float*)d_in[17];
    const float* gb2  =(const float*)d_in[18];
    const float* rpw  =(const float*)d_in[19];
    const float* rpb  =(const float*)d_in[20];
    const float* rs   =(const float*)d_in[21];
    const float* cfw  =(const float*)d_in[22];
    const float* cfb  =(const float*)d_in[23];
    const float* mixs =(const float*)d_in[24];
    float* dout=(float*)d_out;

    k_zero<<<512,256>>>();                                        // 0
    k_prep<<<1024,256>>>(uvs,msk,wg,wb,wh);                       // 1
    k_wtrans<0><<<(3*CIN1P*9*64+255)/256,256>>>(c1w);             // 2
    k_scatter<<<dim3(64,16),256>>>(vf);                           // 3 (profiled slot)
    k_wtrans<1><<<(3*COn*9*64+255)/256,256>>>(c2w);               // 4
    k_finalize<<<512,256>>>();                                    // 5
    k_uncert<<<512,256>>>(dout);                                  // 6
    k_conf<<<512,256>>>(cfw,cfb,dout);                            // 7
    k_conv<C3n,CIN1P,25,0><<<dim3(256,3,2),256>>>(c1b);           // 8
    k_stats<<<1,384>>>(g1s,g1b);                                  // 9
    k_apply<0><<<98304,256>>>();                                  // 10
    k_conv<COn,COn,24,1><<<dim3(256,3,2),256>>>(c2b);             // 11
    k_stats<<<1,384>>>(g2s,g2b);                                  // 12
    k_apply<1><<<98304,256>>>();                                  // 13
    k_gate<<<1,192>>>(gw1,gb1,gw2,gb2);                           // 14
    k_res_combine<<<dim3(256,3,2),256>>>(rpw,rpb,rs,mixs,dout);   // 15
}